// round 4
// baseline (speedup 1.0000x reference)
#include <cuda_runtime.h>
#include <cuda_fp16.h>

// EdgeMLP, gather-minimized form:
//   store per node only x (6 fp16 = one 16B record -> ONE LDG.128 per gather).
//   per edge: sum = xs+xt, dif = xs-xt
//     S = sum @ Ws,  D = dif @ Wd      (Ws=(W1a+W1b)/2, Wd=(W1a-W1b)/2)
//     h_f = relu(S + D + fe *w1e + b1)
//     h_r = relu(S - D + feT*w1e + b1)
//     out = sigmoid( (h_f+h_r) . w2d*0.5 + b2d )   [softmax(2) == sigmoid(diff)]
//   All hidden math in half2 over j-pairs (HFMA2), final combine fp32.

#define N_NODES 100000
#define HID 10

__device__ uint4 g_xtab[N_NODES];   // (x0,x1),(x2,x3),(x4,x5) as half2 + pad
__device__ uint4 g_pp[5][4];        // per j-pair: Ws2[0..5], Wd2[0..5], w1e2, b12, w22, pad
__device__ float g_b2d;

__device__ __forceinline__ __half2 u2h(unsigned int u)
{
    return *reinterpret_cast<__half2*>(&u);
}
__device__ __forceinline__ unsigned int h2u(__half2 h)
{
    return *reinterpret_cast<unsigned int*>(&h);
}

__global__ void precompute_kernel(const float* __restrict__ x,
                                  const float* __restrict__ W1,
                                  const float* __restrict__ b1,
                                  const float* __restrict__ W2,
                                  const float* __restrict__ b2,
                                  int N)
{
    int n = blockIdx.x * blockDim.x + threadIdx.x;

    if (n == 0) {
        for (int jp = 0; jp < 5; ++jp) {
            int j0 = 2 * jp, j1 = 2 * jp + 1;
            unsigned int slot[16];
            for (int i = 0; i < 6; ++i) {
                float a0 = W1[i * HID + j0],       a1 = W1[i * HID + j1];
                float c0 = W1[(6 + i) * HID + j0], c1 = W1[(6 + i) * HID + j1];
                slot[i]     = h2u(__floats2half2_rn(0.5f * (a0 + c0), 0.5f * (a1 + c1))); // Ws
                slot[6 + i] = h2u(__floats2half2_rn(0.5f * (a0 - c0), 0.5f * (a1 - c1))); // Wd
            }
            slot[12] = h2u(__floats2half2_rn(W1[12 * HID + j0], W1[12 * HID + j1]));       // w1e
            slot[13] = h2u(__floats2half2_rn(b1[j0], b1[j1]));                             // b1
            slot[14] = h2u(__floats2half2_rn(0.5f * (W2[j0 * 2 + 1] - W2[j0 * 2]),
                                             0.5f * (W2[j1 * 2 + 1] - W2[j1 * 2])));       // w2diff*0.5
            slot[15] = 0u;
            g_pp[jp][0] = make_uint4(slot[0],  slot[1],  slot[2],  slot[3]);
            g_pp[jp][1] = make_uint4(slot[4],  slot[5],  slot[6],  slot[7]);
            g_pp[jp][2] = make_uint4(slot[8],  slot[9],  slot[10], slot[11]);
            g_pp[jp][3] = make_uint4(slot[12], slot[13], slot[14], slot[15]);
        }
        g_b2d = b2[1] - b2[0];
    }

    if (n >= N) return;

    float x0 = x[n * 6 + 0], x1 = x[n * 6 + 1], x2 = x[n * 6 + 2];
    float x3 = x[n * 6 + 3], x4 = x[n * 6 + 4], x5 = x[n * 6 + 5];
    g_xtab[n] = make_uint4(h2u(__floats2half2_rn(x0, x1)),
                           h2u(__floats2half2_rn(x2, x3)),
                           h2u(__floats2half2_rn(x4, x5)),
                           0u);
}

__device__ __forceinline__ float edge_compute(int s, int t, float fe, float feT,
                                              int N, float b2d)
{
    s = min(max(s, 0), N - 1);
    t = min(max(t, 0), N - 1);

    uint4 xs = __ldg(&g_xtab[s]);
    uint4 xt = __ldg(&g_xtab[t]);

    __half2 sum2[3], dif2[3];
    sum2[0] = __hadd2(u2h(xs.x), u2h(xt.x));  dif2[0] = __hsub2(u2h(xs.x), u2h(xt.x));
    sum2[1] = __hadd2(u2h(xs.y), u2h(xt.y));  dif2[1] = __hsub2(u2h(xs.y), u2h(xt.y));
    sum2[2] = __hadd2(u2h(xs.z), u2h(xt.z));  dif2[2] = __hsub2(u2h(xs.z), u2h(xt.z));

    __half2 bs[6], bd[6];
    #pragma unroll
    for (int k = 0; k < 3; ++k) {
        bs[2 * k]     = __low2half2(sum2[k]);
        bs[2 * k + 1] = __high2half2(sum2[k]);
        bd[2 * k]     = __low2half2(dif2[k]);
        bd[2 * k + 1] = __high2half2(dif2[k]);
    }

    __half2 fe2  = __float2half2_rn(fe);
    __half2 feT2 = __float2half2_rn(feT);
    __half2 zero = __float2half2_rn(0.0f);
    __half2 acc  = zero;

    #pragma unroll
    for (int jp = 0; jp < 5; ++jp) {
        uint4 p0 = __ldg(&g_pp[jp][0]);
        uint4 p1 = __ldg(&g_pp[jp][1]);
        uint4 p2 = __ldg(&g_pp[jp][2]);
        uint4 p3 = __ldg(&g_pp[jp][3]);

        __half2 S = __hmul2(u2h(p0.x), bs[0]);
        S = __hfma2(u2h(p0.y), bs[1], S);
        S = __hfma2(u2h(p0.z), bs[2], S);
        S = __hfma2(u2h(p0.w), bs[3], S);
        S = __hfma2(u2h(p1.x), bs[4], S);
        S = __hfma2(u2h(p1.y), bs[5], S);

        __half2 D = __hmul2(u2h(p1.z), bd[0]);
        D = __hfma2(u2h(p1.w), bd[1], D);
        D = __hfma2(u2h(p2.x), bd[2], D);
        D = __hfma2(u2h(p2.y), bd[3], D);
        D = __hfma2(u2h(p2.z), bd[4], D);
        D = __hfma2(u2h(p2.w), bd[5], D);

        __half2 w1e2 = u2h(p3.x);
        __half2 b12  = u2h(p3.y);
        __half2 w22  = u2h(p3.z);

        __half2 qf = __hfma2(fe2,  w1e2, b12);
        __half2 qr = __hfma2(feT2, w1e2, b12);

        __half2 hf = __hmax2(__hadd2(__hadd2(S, D), qf), zero);
        __half2 hr = __hmax2(__hadd2(__hsub2(S, D), qr), zero);

        acc = __hfma2(__hadd2(hf, hr), w22, acc);
    }

    float2 a = __half22float2(acc);
    float d = a.x + a.y + b2d;
    return 1.0f / (1.0f + __expf(-d));
}

__global__ __launch_bounds__(256)
void edge_kernel(const int* __restrict__ ei,        // [2, E] int32
                 const float* __restrict__ ea,
                 const float* __restrict__ eaT,
                 float* __restrict__ out,
                 int E, int N)
{
    int tid = blockIdx.x * blockDim.x + threadIdx.x;
    int e0 = tid * 2;
    if (e0 >= E) return;

    float b2d = __ldg(&g_b2d);

    if (e0 + 1 < E) {
        int2   ss = *reinterpret_cast<const int2*>(ei + e0);
        int2   tt = *reinterpret_cast<const int2*>(ei + (size_t)E + e0);
        float2 fe = *reinterpret_cast<const float2*>(ea + e0);
        float2 fT = *reinterpret_cast<const float2*>(eaT + e0);

        float2 o;
        o.x = edge_compute(ss.x, tt.x, fe.x, fT.x, N, b2d);
        o.y = edge_compute(ss.y, tt.y, fe.y, fT.y, N, b2d);
        *reinterpret_cast<float2*>(out + e0) = o;
    } else {
        int s = ei[e0];
        int t = ei[(size_t)E + e0];
        out[e0] = edge_compute(s, t, ea[e0], eaT[e0], N, b2d);
    }
}

extern "C" void kernel_launch(void* const* d_in, const int* in_sizes, int n_in,
                              void* d_out, int out_size)
{
    const float* x   = (const float*)d_in[0];
    const int*   ei  = (const int*)d_in[1];
    const float* ea  = (const float*)d_in[2];
    const float* eaT = (const float*)d_in[3];
    const float* W1  = (const float*)d_in[4];
    const float* b1  = (const float*)d_in[5];
    const float* W2  = (const float*)d_in[6];
    const float* b2  = (const float*)d_in[7];
    float*       out = (float*)d_out;

    int N = in_sizes[0] / 6;
    if (N > N_NODES) N = N_NODES;
    int E = in_sizes[2];

    precompute_kernel<<<(N + 255) / 256, 256>>>(x, W1, b1, W2, b2, N);

    int threads_needed = (E + 1) / 2;
    edge_kernel<<<(threads_needed + 255) / 256, 256>>>(ei, ea, eaT, out, E, N);
}

// round 5
// speedup vs baseline: 2.2702x; 2.2702x over previous
#include <cuda_runtime.h>
#include <cuda_fp16.h>

// EdgeMLP, gather-minimized:
//   node table: x in fp16, 16B record -> ONE LDG.128 per endpoint gather.
//   per edge (S/D symmetrization): sum = xs+xt, dif = xs-xt
//     S = sum @ Ws, D = dif @ Wd   (Ws=(W1a+W1b)/2, Wd=(W1a-W1b)/2)
//     h_f = relu(S + D + fe *w1e + b1),  h_r = relu(S - D + feT*w1e + b1)
//     out = sigmoid((h_f+h_r) . (0.5*w2diff) + b2diff)
//   All 75 half2 params live in REGISTERS (loaded once per thread),
//   grid-stride loop with 4 edges/iteration for deep gather pipelining.

#define N_NODES 100000
#define HID 10

__device__ uint4 g_xtab[N_NODES];   // (x0,x1),(x2,x3),(x4,x5) half2 + pad
__device__ uint4 g_pp[5][4];        // per j-pair: Ws[6], Wd[6], w1e, b1, w2d, pad
__device__ float g_b2d;

__device__ __forceinline__ __half2 u2h(unsigned int u)
{
    return *reinterpret_cast<__half2*>(&u);
}
__device__ __forceinline__ unsigned int h2u(__half2 h)
{
    return *reinterpret_cast<unsigned int*>(&h);
}

__global__ void precompute_kernel(const float* __restrict__ x,
                                  const float* __restrict__ W1,
                                  const float* __restrict__ b1,
                                  const float* __restrict__ W2,
                                  const float* __restrict__ b2,
                                  int N)
{
    int n = blockIdx.x * blockDim.x + threadIdx.x;

    if (n == 0) {
        for (int jp = 0; jp < 5; ++jp) {
            int j0 = 2 * jp, j1 = 2 * jp + 1;
            unsigned int slot[16];
            for (int i = 0; i < 6; ++i) {
                float a0 = W1[i * HID + j0],       a1 = W1[i * HID + j1];
                float c0 = W1[(6 + i) * HID + j0], c1 = W1[(6 + i) * HID + j1];
                slot[i]     = h2u(__floats2half2_rn(0.5f * (a0 + c0), 0.5f * (a1 + c1)));
                slot[6 + i] = h2u(__floats2half2_rn(0.5f * (a0 - c0), 0.5f * (a1 - c1)));
            }
            slot[12] = h2u(__floats2half2_rn(W1[12 * HID + j0], W1[12 * HID + j1]));
            slot[13] = h2u(__floats2half2_rn(b1[j0], b1[j1]));
            slot[14] = h2u(__floats2half2_rn(0.5f * (W2[j0 * 2 + 1] - W2[j0 * 2]),
                                             0.5f * (W2[j1 * 2 + 1] - W2[j1 * 2])));
            slot[15] = 0u;
            g_pp[jp][0] = make_uint4(slot[0],  slot[1],  slot[2],  slot[3]);
            g_pp[jp][1] = make_uint4(slot[4],  slot[5],  slot[6],  slot[7]);
            g_pp[jp][2] = make_uint4(slot[8],  slot[9],  slot[10], slot[11]);
            g_pp[jp][3] = make_uint4(slot[12], slot[13], slot[14], slot[15]);
        }
        g_b2d = b2[1] - b2[0];
    }

    if (n >= N) return;

    float x0 = x[n * 6 + 0], x1 = x[n * 6 + 1], x2 = x[n * 6 + 2];
    float x3 = x[n * 6 + 3], x4 = x[n * 6 + 4], x5 = x[n * 6 + 5];
    g_xtab[n] = make_uint4(h2u(__floats2half2_rn(x0, x1)),
                           h2u(__floats2half2_rn(x2, x3)),
                           h2u(__floats2half2_rn(x4, x5)),
                           0u);
}

struct Params {
    __half2 ws[5][6];
    __half2 wd[5][6];
    __half2 w1e[5];
    __half2 b1h[5];
    __half2 w2h[5];
};

__device__ __forceinline__ float edge_one(uint4 xs, uint4 xt, float fe, float feT,
                                          const Params& P, float b2d)
{
    __half2 sum0 = __hadd2(u2h(xs.x), u2h(xt.x));
    __half2 sum1 = __hadd2(u2h(xs.y), u2h(xt.y));
    __half2 sum2 = __hadd2(u2h(xs.z), u2h(xt.z));
    __half2 dif0 = __hsub2(u2h(xs.x), u2h(xt.x));
    __half2 dif1 = __hsub2(u2h(xs.y), u2h(xt.y));
    __half2 dif2 = __hsub2(u2h(xs.z), u2h(xt.z));

    __half2 bs[6] = { __low2half2(sum0), __high2half2(sum0),
                      __low2half2(sum1), __high2half2(sum1),
                      __low2half2(sum2), __high2half2(sum2) };
    __half2 bd[6] = { __low2half2(dif0), __high2half2(dif0),
                      __low2half2(dif1), __high2half2(dif1),
                      __low2half2(dif2), __high2half2(dif2) };

    __half2 fe2  = __float2half2_rn(fe);
    __half2 feT2 = __float2half2_rn(feT);
    __half2 zero = __float2half2_rn(0.0f);
    __half2 acc  = zero;

    #pragma unroll
    for (int jp = 0; jp < 5; ++jp) {
        __half2 S = __hmul2(P.ws[jp][0], bs[0]);
        S = __hfma2(P.ws[jp][1], bs[1], S);
        S = __hfma2(P.ws[jp][2], bs[2], S);
        S = __hfma2(P.ws[jp][3], bs[3], S);
        S = __hfma2(P.ws[jp][4], bs[4], S);
        S = __hfma2(P.ws[jp][5], bs[5], S);

        __half2 D = __hmul2(P.wd[jp][0], bd[0]);
        D = __hfma2(P.wd[jp][1], bd[1], D);
        D = __hfma2(P.wd[jp][2], bd[2], D);
        D = __hfma2(P.wd[jp][3], bd[3], D);
        D = __hfma2(P.wd[jp][4], bd[4], D);
        D = __hfma2(P.wd[jp][5], bd[5], D);

        __half2 qf = __hfma2(fe2,  P.w1e[jp], P.b1h[jp]);
        __half2 qr = __hfma2(feT2, P.w1e[jp], P.b1h[jp]);

        __half2 hf = __hmax2(__hadd2(__hadd2(S, D), qf), zero);
        __half2 hr = __hmax2(__hadd2(__hsub2(S, D), qr), zero);

        acc = __hfma2(__hadd2(hf, hr), P.w2h[jp], acc);
    }

    float2 a = __half22float2(acc);
    float d = a.x + a.y + b2d;
    return 1.0f / (1.0f + __expf(-d));
}

__global__ __launch_bounds__(256, 2)
void edge_kernel(const int* __restrict__ ei,        // [2, E] int32
                 const float* __restrict__ ea,
                 const float* __restrict__ eaT,
                 float* __restrict__ out,
                 int E, int N)
{
    // ---- load all parameters into registers once per thread ----
    Params P;
    #pragma unroll
    for (int jp = 0; jp < 5; ++jp) {
        uint4 p0 = __ldg(&g_pp[jp][0]);
        uint4 p1 = __ldg(&g_pp[jp][1]);
        uint4 p2 = __ldg(&g_pp[jp][2]);
        uint4 p3 = __ldg(&g_pp[jp][3]);
        P.ws[jp][0] = u2h(p0.x); P.ws[jp][1] = u2h(p0.y);
        P.ws[jp][2] = u2h(p0.z); P.ws[jp][3] = u2h(p0.w);
        P.ws[jp][4] = u2h(p1.x); P.ws[jp][5] = u2h(p1.y);
        P.wd[jp][0] = u2h(p1.z); P.wd[jp][1] = u2h(p1.w);
        P.wd[jp][2] = u2h(p2.x); P.wd[jp][3] = u2h(p2.y);
        P.wd[jp][4] = u2h(p2.z); P.wd[jp][5] = u2h(p2.w);
        P.w1e[jp] = u2h(p3.x);
        P.b1h[jp] = u2h(p3.y);
        P.w2h[jp] = u2h(p3.z);
    }
    float b2d = __ldg(&g_b2d);

    int Nm1 = N - 1;
    int stride = gridDim.x * blockDim.x;
    int tid = blockIdx.x * blockDim.x + threadIdx.x;

    if ((E & 3) == 0) {
        int nq = E >> 2;
        for (int q = tid; q < nq; q += stride) {
            int e0 = q << 2;
            int4   ss = *reinterpret_cast<const int4*>(ei + e0);
            int4   tt = *reinterpret_cast<const int4*>(ei + (size_t)E + e0);
            float4 fe = *reinterpret_cast<const float4*>(ea + e0);
            float4 fT = *reinterpret_cast<const float4*>(eaT + e0);

            int s0 = min(max(ss.x, 0), Nm1), t0 = min(max(tt.x, 0), Nm1);
            int s1 = min(max(ss.y, 0), Nm1), t1 = min(max(tt.y, 0), Nm1);
            int s2 = min(max(ss.z, 0), Nm1), t2 = min(max(tt.z, 0), Nm1);
            int s3 = min(max(ss.w, 0), Nm1), t3 = min(max(tt.w, 0), Nm1);

            // issue all 8 gathers up front (deep MLP)
            uint4 xs0 = __ldg(&g_xtab[s0]);
            uint4 xt0 = __ldg(&g_xtab[t0]);
            uint4 xs1 = __ldg(&g_xtab[s1]);
            uint4 xt1 = __ldg(&g_xtab[t1]);
            uint4 xs2 = __ldg(&g_xtab[s2]);
            uint4 xt2 = __ldg(&g_xtab[t2]);
            uint4 xs3 = __ldg(&g_xtab[s3]);
            uint4 xt3 = __ldg(&g_xtab[t3]);

            float4 o;
            o.x = edge_one(xs0, xt0, fe.x, fT.x, P, b2d);
            o.y = edge_one(xs1, xt1, fe.y, fT.y, P, b2d);
            o.z = edge_one(xs2, xt2, fe.z, fT.z, P, b2d);
            o.w = edge_one(xs3, xt3, fe.w, fT.w, P, b2d);
            *reinterpret_cast<float4*>(out + e0) = o;
        }
    } else {
        for (int e = tid; e < E; e += stride) {
            int s = min(max(ei[e], 0), Nm1);
            int t = min(max(ei[(size_t)E + e], 0), Nm1);
            uint4 xs = __ldg(&g_xtab[s]);
            uint4 xt = __ldg(&g_xtab[t]);
            out[e] = edge_one(xs, xt, ea[e], eaT[e], P, b2d);
        }
    }
}

extern "C" void kernel_launch(void* const* d_in, const int* in_sizes, int n_in,
                              void* d_out, int out_size)
{
    const float* x   = (const float*)d_in[0];
    const int*   ei  = (const int*)d_in[1];
    const float* ea  = (const float*)d_in[2];
    const float* eaT = (const float*)d_in[3];
    const float* W1  = (const float*)d_in[4];
    const float* b1  = (const float*)d_in[5];
    const float* W2  = (const float*)d_in[6];
    const float* b2  = (const float*)d_in[7];
    float*       out = (float*)d_out;

    int N = in_sizes[0] / 6;
    if (N > N_NODES) N = N_NODES;
    int E = in_sizes[2];

    precompute_kernel<<<(N + 255) / 256, 256>>>(x, W1, b1, W2, b2, N);

    int work_items = (E + 3) / 4;                 // quads in vector path
    int blocks = 592;                             // 148 SMs x 4 (2 resident/SM)
    int max_blocks = (work_items + 255) / 256;
    if (blocks > max_blocks) blocks = max_blocks;
    if (blocks < 1) blocks = 1;
    edge_kernel<<<blocks, 256>>>(ei, ea, eaT, out, E, N);
}